// round 10
// baseline (speedup 1.0000x reference)
#include <cuda_runtime.h>
#include <math.h>
#include <stdint.h>

// Problem dims
#define BB 32
#define SS 2048
#define II 128
#define HH 512
#define OO 128

#define RGRID 128
#define CLUS 16          // CTAs per cluster
#define CPT 32           // columns per CTA
#define HPAD 520         // 512 + 8 pad: b*520 -> bank offset b*8 (conflict-free)
#define WSZ (CPT * 512)  // per-gate weight floats in SMEM

// ---------------- static device scratch ----------------
__device__ float g_Abuf[SS * BB * 1536];  // x-projections [t][b][z|r|g]
__device__ float g_H0[SS * BB * HH];
__device__ float g_H1[SS * BB * HH];
__device__ float g_hc[2 * BB * HH];

// ---------------- cluster helpers ----------------
#define CLUSTER_SYNC() do { \
    asm volatile("barrier.cluster.arrive.aligned;" ::: "memory"); \
    asm volatile("barrier.cluster.wait.aligned;"   ::: "memory"); } while (0)

__device__ __forceinline__ uint32_t mapa_u32(uint32_t laddr, int rank) {
    uint32_t r;
    asm("mapa.shared::cluster.u32 %0, %1, %2;" : "=r"(r) : "r"(laddr), "r"(rank));
    return r;
}
__device__ __forceinline__ void stc_f32(uint32_t raddr, float v) {
    asm volatile("st.shared::cluster.f32 [%0], %1;" :: "r"(raddr), "f"(v) : "memory");
}

// ---------------- SGEMM (unchanged, known-good) ----------------
__global__ __launch_bounds__(256, 2) void sgemm_kernel(
    const float* __restrict__ A, int amode, int K,
    const float* __restrict__ W0g, const float* __restrict__ W1g, const float* __restrict__ W2g,
    const float* __restrict__ b0g, const float* __restrict__ b1g, const float* __restrict__ b2g,
    int ngate, float* __restrict__ C, int omode, int ldc)
{
    __shared__ float As[8][128];
    __shared__ float Bs[8][132];

    const int tid = threadIdx.x;
    const int bm = blockIdx.x;
    const int ncol0 = blockIdx.y * 128;
    const int gate = ncol0 / ngate;
    const float* W    = (gate == 0) ? W0g : (gate == 1) ? W1g : W2g;
    const float* bias = (gate == 0) ? b0g : (gate == 1) ? b1g : b2g;
    const int ng_off = ncol0 - gate * ngate;

    const int tx = tid & 15;
    const int ty = tid >> 4;

    float acc[8][8];
#pragma unroll
    for (int i = 0; i < 8; i++)
#pragma unroll
        for (int j = 0; j < 8; j++) acc[i][j] = 0.f;

    const int arow = tid >> 1;
    const int ak = (tid & 1) * 4;
    const int grow = bm * 128 + arow;
    long aoff;
    if (amode == 0) aoff = (long)(grow & 31) * (SS * II) + (long)(grow >> 5) * II;
    else            aoff = (long)grow * K;

    const int bk = tid >> 5;
    const int bn = (tid & 31) * 4;

    for (int kk = 0; kk < K; kk += 8) {
        float4 av = *(const float4*)(A + aoff + (kk + ak));
        As[ak + 0][arow] = av.x;
        As[ak + 1][arow] = av.y;
        As[ak + 2][arow] = av.z;
        As[ak + 3][arow] = av.w;
        float4 wv = *(const float4*)(W + (long)(kk + bk) * ngate + (ng_off + bn));
        *(float4*)&Bs[bk][bn] = wv;
        __syncthreads();
#pragma unroll
        for (int k = 0; k < 8; k++) {
            float rm[8], rn[8];
            *(float4*)&rm[0] = *(const float4*)&As[k][ty * 8];
            *(float4*)&rm[4] = *(const float4*)&As[k][ty * 8 + 4];
            *(float4*)&rn[0] = *(const float4*)&Bs[k][tx * 8];
            *(float4*)&rn[4] = *(const float4*)&Bs[k][tx * 8 + 4];
#pragma unroll
            for (int i = 0; i < 8; i++)
#pragma unroll
                for (int j = 0; j < 8; j++)
                    acc[i][j] += rm[i] * rn[j];
        }
        __syncthreads();
    }

#pragma unroll
    for (int i = 0; i < 8; i++) {
        int row = bm * 128 + ty * 8 + i;
        long obase;
        if (omode == 0) obase = (long)row * ldc + ncol0;
        else            obase = (long)(row & 31) * (SS * OO) + (long)(row >> 5) * OO + ncol0;
#pragma unroll
        for (int j = 0; j < 8; j++)
            C[obase + tx * 8 + j] = acc[i][j] + bias[ng_off + tx * 8 + j];
    }
}

// ---------------- clustered GRU recurrence ----------------
// Cluster (16 CTAs) owns 4 batches; CTA rank owns columns [32r, 32r+32).
// All recurrent weights for the CTA's 32 cols live in SMEM (192 KB, XOR-swizzled).
// h and r*h are cluster-local: each CTA keeps a FULL copy (4 batches x 512),
// refreshed by DSMEM pushes from peers + barrier.cluster. No grid-wide sync.
__global__ void __launch_bounds__(256, 1) gru_cluster_kernel(
    const float* __restrict__ Abuf,
    const float* __restrict__ Whz, const float* __restrict__ Whr, const float* __restrict__ Whg,
    const float* __restrict__ hinit, float* __restrict__ Hout)
{
    extern __shared__ float smf[];
    float* wz   = smf;                   // [32][512] swizzled
    float* wr   = wz + WSZ;
    float* wg   = wr + WSZ;
    float* h_s  = wg + WSZ;              // [4][HPAD] full h (cluster's 4 batches)
    float* rh_s = h_s + 4 * HPAD;        // [4][HPAD] full r*h
    float* red  = rh_s + 4 * HPAD;       // [8 warps][2 gates][4b x 33 + col]
    float* z_s  = red + 8 * 264;         // [32 cols][4 b]

    const int tid = threadIdx.x;
    int rank;
    asm("mov.u32 %0, %%cluster_ctarank;" : "=r"(rank));
    const int cl = blockIdx.x >> 4;          // cluster id
    const int gc0 = rank * CPT;              // global column base
    const int b0 = cl * 4;                   // global batch base

    const int lane = tid & 31, kw = tid >> 5;
    const int kbase = kw * 64;
    const int lb = lane >> 3;                // batch 0..3
    const int cgrp = lane & 7;               // col group of 4
    const int cc0 = cgrp * 4;

    // reduce mapping
    const int rg  = tid >> 7;                // 0 = z, 1 = r
    const int rcc = (tid >> 2) & 31;         // local col
    const int rbb = tid & 3;                 // batch

    // ---- stage weights (swizzled: w4 for (cc, f) at cc*512 + ((f^(cc>>2))<<2)) ----
    for (int idx = tid; idx < 3 * WSZ; idx += 256) {
        int m = idx >> 14;                   // gate
        int rem = idx & (WSZ - 1);
        int cc = rem >> 9, k = rem & 511;
        const float* Wm = (m == 0) ? Whz : (m == 1) ? Whr : Whg;
        float v = Wm[k * 512 + gc0 + cc];
        int f = k >> 2, ki = k & 3;
        smf[m * WSZ + cc * 512 + (((f ^ (cc >> 2)) << 2) + ki)] = v;
    }
    // ---- stage initial h: full 512 cols x 4 batches ----
    for (int idx = tid; idx < 4 * 512; idx += 256) {
        int b = idx >> 9, c = idx & 511;
        h_s[b * HPAD + c] = hinit[(b0 + b) * 512 + c];
    }
    __syncthreads();
    CLUSTER_SYNC();          // all peers' initial staging done before any push

    // precompute DSMEM destinations for my (rcc, rbb) value in every peer CTA
    uint32_t rh_l = (uint32_t)__cvta_generic_to_shared(&rh_s[rbb * HPAD + gc0 + rcc]);
    uint32_t h_l  = (uint32_t)__cvta_generic_to_shared(&h_s[rbb * HPAD + gc0 + rcc]);
    uint32_t rdst_rh[CLUS], rdst_h[CLUS];
#pragma unroll
    for (int p = 0; p < CLUS; p++) {
        rdst_rh[p] = mapa_u32(rh_l, p);
        rdst_h[p]  = mapa_u32(h_l, p);
    }

    // prefetch t=0 Abuf terms
    float pA, pG = 0.f;
    {
        const float* ab = Abuf + (size_t)(b0 + rbb) * 1536;
        pA = __ldg(ab + rg * 512 + gc0 + rcc);
        if (tid < 128) pG = __ldg(ab + 1024 + gc0 + rcc);
    }

    for (int t = 0; t < SS; t++) {
        // ---- Phase A dot: z & r, 4 cols x 2 gates per lane, K-chunk 64 ----
        {
            float az[4] = {0.f, 0.f, 0.f, 0.f};
            float ar[4] = {0.f, 0.f, 0.f, 0.f};
            const float* hp = h_s + lb * HPAD + kbase;
#pragma unroll
            for (int k4 = 0; k4 < 16; k4++) {
                float4 h4 = *(const float4*)(hp + k4 * 4);
                int fs = (((kbase >> 2) + k4) ^ cgrp) << 2;
#pragma unroll
                for (int ci = 0; ci < 4; ci++) {
                    float4 w1 = *(const float4*)(wz + (cc0 + ci) * 512 + fs);
                    az[ci] += h4.x * w1.x + h4.y * w1.y + h4.z * w1.z + h4.w * w1.w;
                    float4 w2 = *(const float4*)(wr + (cc0 + ci) * 512 + fs);
                    ar[ci] += h4.x * w2.x + h4.y * w2.y + h4.z * w2.z + h4.w * w2.w;
                }
            }
#pragma unroll
            for (int ci = 0; ci < 4; ci++) {
                red[kw * 264 +       lb * 33 + cc0 + ci] = az[ci];
                red[kw * 264 + 132 + lb * 33 + cc0 + ci] = ar[ci];
            }
        }
        __syncthreads();

        // ---- Phase A reduce + activations + rh push ----
        {
            float s = pA;
#pragma unroll
            for (int w = 0; w < 8; w++)
                s += red[w * 264 + rg * 132 + rbb * 33 + rcc];
            float sg = 1.f / (1.f + __expf(-s));
            if (rg == 0) {
                z_s[rcc * 4 + rbb] = sg;
            } else {
                float rh = sg * h_s[rbb * HPAD + gc0 + rcc];
#pragma unroll
                for (int p = 0; p < CLUS; p++) stc_f32(rdst_rh[p], rh);
            }
        }
        CLUSTER_SYNC();

        // ---- Phase B dot: g, 4 cols per lane ----
        {
            float ag[4] = {0.f, 0.f, 0.f, 0.f};
            const float* rp = rh_s + lb * HPAD + kbase;
#pragma unroll
            for (int k4 = 0; k4 < 16; k4++) {
                float4 h4 = *(const float4*)(rp + k4 * 4);
                int fs = (((kbase >> 2) + k4) ^ cgrp) << 2;
#pragma unroll
                for (int ci = 0; ci < 4; ci++) {
                    float4 w1 = *(const float4*)(wg + (cc0 + ci) * 512 + fs);
                    ag[ci] += h4.x * w1.x + h4.y * w1.y + h4.z * w1.z + h4.w * w1.w;
                }
            }
#pragma unroll
            for (int ci = 0; ci < 4; ci++)
                red[kw * 264 + lb * 33 + cc0 + ci] = ag[ci];
        }
        __syncthreads();

        // ---- Phase B reduce + h update + push new h ----
        if (tid < 128) {
            float s = pG;
#pragma unroll
            for (int w = 0; w < 8; w++)
                s += red[w * 264 + rbb * 33 + rcc];
            float g = tanhf(s);
            float z = z_s[rcc * 4 + rbb];
            float ho = h_s[rbb * HPAD + gc0 + rcc];
            float hn = z * ho + (1.f - z) * g;
#pragma unroll
            for (int p = 0; p < CLUS; p++) stc_f32(rdst_h[p], hn);
            Hout[(size_t)(t * 32 + b0 + rbb) * 512 + gc0 + rcc] = hn;
        }
        // prefetch next step's Abuf terms (hidden under peers' phase B)
        if (t + 1 < SS) {
            const float* ab = Abuf + (size_t)((t + 1) * 32 + b0 + rbb) * 1536;
            pA = __ldg(ab + rg * 512 + gc0 + rcc);
            if (tid < 128) pG = __ldg(ab + 1024 + gc0 + rcc);
        }
        CLUSTER_SYNC();
    }
}

// ---------------- small helpers ----------------
__global__ void init_h_kernel(const float* __restrict__ h0, float* __restrict__ hc) {
    int i = blockIdx.x * 256 + threadIdx.x;
    if (i < 2 * BB * HH) {
        int l = i >> 14, rem = i & 16383, b = rem >> 9, h = rem & 511;
        hc[i] = h0[b * 1024 + l * 512 + h];
    }
}

__global__ void copy_hidden_kernel(float* __restrict__ out,
                                   const float* __restrict__ H0f,
                                   const float* __restrict__ H1f) {
    int i = blockIdx.x * 256 + threadIdx.x;   // (B, L, H)
    if (i < BB * 2 * HH) {
        int b = i >> 10, rem = i & 1023;
        int l = rem >> 9, h = rem & 511;
        const float* src = l ? H1f : H0f;
        out[i] = src[(size_t)((SS - 1) * 32 + b) * 512 + h];
    }
}

// ---------------- launch ----------------
extern "C" void kernel_launch(void* const* d_in, const int* in_sizes, int n_in,
                              void* d_out, int out_size)
{
    const float* x    = (const float*)d_in[0];
    const float* h0   = (const float*)d_in[1];
    const float* W0xz = (const float*)d_in[2];
    const float* W0hz = (const float*)d_in[3];
    const float* b0z  = (const float*)d_in[4];
    const float* W0xr = (const float*)d_in[5];
    const float* W0hr = (const float*)d_in[6];
    const float* b0r  = (const float*)d_in[7];
    const float* W0xg = (const float*)d_in[8];
    const float* W0hg = (const float*)d_in[9];
    const float* b0g  = (const float*)d_in[10];
    const float* W1xz = (const float*)d_in[11];
    const float* W1hz = (const float*)d_in[12];
    const float* b1z  = (const float*)d_in[13];
    const float* W1xr = (const float*)d_in[14];
    const float* W1hr = (const float*)d_in[15];
    const float* b1r  = (const float*)d_in[16];
    const float* W1xg = (const float*)d_in[17];
    const float* W1hg = (const float*)d_in[18];
    const float* b1g  = (const float*)d_in[19];
    const float* Wy   = (const float*)d_in[20];
    const float* by   = (const float*)d_in[21];
    float* out = (float*)d_out;

    float *Abuf, *H0, *H1, *hc;
    cudaGetSymbolAddress((void**)&Abuf, g_Abuf);
    cudaGetSymbolAddress((void**)&H0,   g_H0);
    cudaGetSymbolAddress((void**)&H1,   g_H1);
    cudaGetSymbolAddress((void**)&hc,   g_hc);

    // smem: 3 gates * 32*512 + h 4*520 + rh 4*520 + red 8*264 + z 128
    const size_t smem = (size_t)(3 * WSZ + 8 * HPAD + 8 * 264 + 128) * sizeof(float);
    cudaFuncSetAttribute(gru_cluster_kernel,
                         cudaFuncAttributeMaxDynamicSharedMemorySize, (int)smem);
    cudaFuncSetAttribute(gru_cluster_kernel,
                         cudaFuncAttributeNonPortableClusterSizeAllowed, 1);

    cudaLaunchConfig_t cfg = {};
    cfg.gridDim = dim3(RGRID, 1, 1);
    cfg.blockDim = dim3(256, 1, 1);
    cfg.dynamicSmemBytes = smem;
    cfg.stream = 0;
    cudaLaunchAttribute at[1];
    at[0].id = cudaLaunchAttributeClusterDimension;
    at[0].val.clusterDim.x = CLUS;
    at[0].val.clusterDim.y = 1;
    at[0].val.clusterDim.z = 1;
    cfg.attrs = at;
    cfg.numAttrs = 1;

    init_h_kernel<<<128, 256>>>(h0, hc);

    dim3 gproj(512, 12);  // M=65536/128, N=1536/128

    // layer 0
    sgemm_kernel<<<gproj, 256>>>(x, 0, II, W0xz, W0xr, W0xg, b0z, b0r, b0g,
                                 512, Abuf, 0, 1536);
    cudaLaunchKernelEx(&cfg, gru_cluster_kernel,
                       (const float*)Abuf, W0hz, W0hr, W0hg,
                       (const float*)hc, H0);

    // layer 1
    sgemm_kernel<<<gproj, 256>>>(H0, 1, HH, W1xz, W1xr, W1xg, b1z, b1r, b1g,
                                 512, Abuf, 0, 1536);
    cudaLaunchKernelEx(&cfg, gru_cluster_kernel,
                       (const float*)Abuf, W1hz, W1hr, W1hg,
                       (const float*)(hc + BB * HH), H1);

    // output head
    dim3 ghead(512, 1);
    sgemm_kernel<<<ghead, 256>>>(H1, 1, HH, Wy, Wy, Wy, by, by, by,
                                 128, out, 1, 0);

    if (out_size >= BB * SS * OO + BB * 2 * HH) {
        copy_hidden_kernel<<<128, 256>>>(out + BB * SS * OO, H0, H1);
    }
}

// round 11
// speedup vs baseline: 2.0889x; 2.0889x over previous
#include <cuda_runtime.h>
#include <math.h>
#include <stdint.h>

// Problem dims
#define BB 32
#define SS 2048
#define II 128
#define HH 512
#define OO 128

#define RGRID 128        // 8 groups x 16 CTAs
#define WSZ (32 * 512)   // per-gate weight floats in SMEM (32 cols)

// ---------------- static device scratch ----------------
__device__ float g_Abuf[SS * BB * 1536];  // x-projections [t][b][z|r|g]
__device__ float g_H0[SS * BB * HH];
__device__ float g_H1[SS * BB * HH];
__device__ float g_hx[BB * HH];           // group-exchanged h   [gbatch][512]
__device__ float g_rhx[BB * HH];          // group-exchanged r*h [gbatch][512]
__device__ unsigned g_gbar[8 * 32];       // per-group barrier counters (128B apart)

// ---------------- cp.async helpers ----------------
__device__ __forceinline__ void cp_async16(void* smem, const void* gmem) {
    unsigned s = (unsigned)__cvta_generic_to_shared(smem);
    asm volatile("cp.async.cg.shared.global [%0], [%1], 16;" :: "r"(s), "l"(gmem));
}
__device__ __forceinline__ void cp_commit() {
    asm volatile("cp.async.commit_group;");
}
template<int N> __device__ __forceinline__ void cp_wait() {
    asm volatile("cp.async.wait_group %0;" :: "n"(N));
}

// ---------------- per-group barrier (16 arrivals) ----------------
__device__ __forceinline__ void grp_arrive(unsigned* bar) {
    asm volatile("red.release.gpu.global.add.u32 [%0], %1;"
                 :: "l"(bar), "r"(1u) : "memory");
}
__device__ __forceinline__ void grp_wait(unsigned* bar, unsigned tgt) {
    unsigned v;
    do {
        asm volatile("ld.acquire.gpu.global.u32 %0, [%1];"
                     : "=r"(v) : "l"(bar) : "memory");
    } while (v < tgt);
}

__global__ void reset_bar_kernel() {
    int i = threadIdx.x;
    if (i < 8) g_gbar[i * 32] = 0;
}

// init group-exchange h from h0 (B, L, H) for one layer
__global__ void init_hx_kernel(const float* __restrict__ h0, int layer) {
    int i = blockIdx.x * 256 + threadIdx.x;   // 32*512
    if (i < BB * HH) {
        int gb = i >> 9, c = i & 511;
        g_hx[i] = h0[gb * 1024 + layer * 512 + c];
    }
}

// ---------------- SGEMM (unchanged, known-good) ----------------
__global__ __launch_bounds__(256, 2) void sgemm_kernel(
    const float* __restrict__ A, int amode, int K,
    const float* __restrict__ W0g, const float* __restrict__ W1g, const float* __restrict__ W2g,
    const float* __restrict__ b0g, const float* __restrict__ b1g, const float* __restrict__ b2g,
    int ngate, float* __restrict__ C, int omode, int ldc)
{
    __shared__ float As[8][128];
    __shared__ float Bs[8][132];

    const int tid = threadIdx.x;
    const int bm = blockIdx.x;
    const int ncol0 = blockIdx.y * 128;
    const int gate = ncol0 / ngate;
    const float* W    = (gate == 0) ? W0g : (gate == 1) ? W1g : W2g;
    const float* bias = (gate == 0) ? b0g : (gate == 1) ? b1g : b2g;
    const int ng_off = ncol0 - gate * ngate;

    const int tx = tid & 15;
    const int ty = tid >> 4;

    float acc[8][8];
#pragma unroll
    for (int i = 0; i < 8; i++)
#pragma unroll
        for (int j = 0; j < 8; j++) acc[i][j] = 0.f;

    const int arow = tid >> 1;
    const int ak = (tid & 1) * 4;
    const int grow = bm * 128 + arow;
    long aoff;
    if (amode == 0) aoff = (long)(grow & 31) * (SS * II) + (long)(grow >> 5) * II;
    else            aoff = (long)grow * K;

    const int bk = tid >> 5;
    const int bn = (tid & 31) * 4;

    for (int kk = 0; kk < K; kk += 8) {
        float4 av = *(const float4*)(A + aoff + (kk + ak));
        As[ak + 0][arow] = av.x;
        As[ak + 1][arow] = av.y;
        As[ak + 2][arow] = av.z;
        As[ak + 3][arow] = av.w;
        float4 wv = *(const float4*)(W + (long)(kk + bk) * ngate + (ng_off + bn));
        *(float4*)&Bs[bk][bn] = wv;
        __syncthreads();
#pragma unroll
        for (int k = 0; k < 8; k++) {
            float rm[8], rn[8];
            *(float4*)&rm[0] = *(const float4*)&As[k][ty * 8];
            *(float4*)&rm[4] = *(const float4*)&As[k][ty * 8 + 4];
            *(float4*)&rn[0] = *(const float4*)&Bs[k][tx * 8];
            *(float4*)&rn[4] = *(const float4*)&Bs[k][tx * 8 + 4];
#pragma unroll
            for (int i = 0; i < 8; i++)
#pragma unroll
                for (int j = 0; j < 8; j++)
                    acc[i][j] += rm[i] * rn[j];
        }
        __syncthreads();
    }

#pragma unroll
    for (int i = 0; i < 8; i++) {
        int row = bm * 128 + ty * 8 + i;
        long obase;
        if (omode == 0) obase = (long)row * ldc + ncol0;
        else            obase = (long)(row & 31) * (SS * OO) + (long)(row >> 5) * OO + ncol0;
#pragma unroll
        for (int j = 0; j < 8; j++)
            C[obase + tx * 8 + j] = acc[i][j] + bias[ng_off + tx * 8 + j];
    }
}

// ---------------- grouped GRU recurrence ----------------
// Group = 16 CTAs = 4 batches (b0..b0+3); CTA rank owns 32 columns.
// All exchange (r*h, h) stays inside the group -> 16-arrival barrier.
// Weights for the CTA's 32 cols of all 3 gates live in SMEM (192 KB, swizzled).
__global__ void __launch_bounds__(256, 1) gru_group_kernel(
    const float* __restrict__ Abuf,
    const float* __restrict__ Whz, const float* __restrict__ Whr, const float* __restrict__ Whg,
    float* __restrict__ Hout)
{
    extern __shared__ float smf[];
    float* wz   = smf;                 // [32][512] swizzled
    float* wr   = wz + WSZ;
    float* wg   = wr + WSZ;
    float* h_s  = wg + WSZ;            // [4][520]
    float* rh_s = h_s + 4 * 520;       // [4][520]
    float* red  = rh_s + 4 * 520;      // [8 warps][264] : g*132 + b*33 + col
    float* z_s  = red + 8 * 264;       // [128] : b*32 + col

    const int tid = threadIdx.x;
    const int cta = blockIdx.x;
    const int gid = cta >> 4, rank = cta & 15;
    const int c0 = rank * 32;
    const int b0 = gid * 4;
    const int lane = tid & 31, kw = tid >> 5;
    const int kbase = kw * 64;
    const int lb = lane & 3;           // batch within group
    const int cg = lane >> 2;          // col group of 4
    const int cc0 = cg * 4;
    // reduce mapping
    const int rg = tid >> 7;           // 0=z, 1=r
    const int rb = (tid >> 5) & 3;
    const int rcol = tid & 31;

    // ---- stage weights swizzled: (cc,f) at cc*512 + ((f^(cc>>2))<<2 | ki) ----
    for (int idx = tid; idx < 3 * WSZ; idx += 256) {
        int m = idx >> 14;
        int rem = idx & 16383;
        int cc = rem >> 9, k = rem & 511;
        const float* Wm = (m == 0) ? Whz : (m == 1) ? Whr : Whg;
        float v = Wm[k * 512 + c0 + cc];
        int f = k >> 2, ki = k & 3;
        smf[m * WSZ + cc * 512 + ((((f ^ (cc >> 2)) << 2)) | ki)] = v;
    }
    __syncthreads();

    unsigned* bar = &g_gbar[gid * 32];
    unsigned ep = 0;

    // t=0 Abuf prefetch
    float pA, pG = 0.f;
    {
        const float* ab = Abuf + (size_t)(b0 + rb) * 1536;
        pA = __ldg(ab + rg * 512 + c0 + rcol);
        if (tid < 128) pG = __ldg(ab + 1024 + c0 + rcol);
    }

    for (int t = 0; t < SS; t++) {
        // ---- stage h (4x512 = 8KB) ----
#pragma unroll
        for (int i = 0; i < 2; i++) {
            int e = i * 256 + tid;         // 0..511 float4
            int b = e >> 7, f4 = e & 127;
            cp_async16(&h_s[b * 520 + f4 * 4], g_hx + gid * 2048 + b * 512 + f4 * 4);
        }
        cp_commit(); cp_wait<0>(); __syncthreads();

        // ---- Phase A dot: z & r, 4 cols x 2 gates per lane over K-chunk 64 ----
        {
            float az[4] = {0.f, 0.f, 0.f, 0.f};
            float ar[4] = {0.f, 0.f, 0.f, 0.f};
            const float* hp = h_s + lb * 520 + kbase;
#pragma unroll
            for (int k4 = 0; k4 < 16; k4++) {
                float4 h4 = *(const float4*)(hp + k4 * 4);
                int fs = ((((kbase >> 2) + k4) ^ cg) << 2);
#pragma unroll
                for (int ci = 0; ci < 4; ci++) {
                    float4 w1 = *(const float4*)(wz + (cc0 + ci) * 512 + fs);
                    az[ci] += h4.x * w1.x + h4.y * w1.y + h4.z * w1.z + h4.w * w1.w;
                    float4 w2 = *(const float4*)(wr + (cc0 + ci) * 512 + fs);
                    ar[ci] += h4.x * w2.x + h4.y * w2.y + h4.z * w2.z + h4.w * w2.w;
                }
            }
#pragma unroll
            for (int ci = 0; ci < 4; ci++) {
                red[kw * 264 +       lb * 33 + cc0 + ci] = az[ci];
                red[kw * 264 + 132 + lb * 33 + cc0 + ci] = ar[ci];
            }
        }
        __syncthreads();

        // ---- Phase A reduce + activations + rh store ----
        {
            float s = pA;
#pragma unroll
            for (int w = 0; w < 8; w++) s += red[w * 264 + rg * 132 + rb * 33 + rcol];
            float sg = 1.f / (1.f + __expf(-s));
            if (rg == 0) {
                z_s[rb * 32 + rcol] = sg;
            } else {
                float rh = sg * h_s[rb * 520 + c0 + rcol];
                __stcg(&g_rhx[gid * 2048 + rb * 512 + c0 + rcol], rh);
            }
        }
        __syncthreads();
        if (tid == 0) grp_arrive(bar);
        ep++;
        if (tid == 0) grp_wait(bar, ep * 16);
        __syncthreads();

        // ---- stage r*h ----
#pragma unroll
        for (int i = 0; i < 2; i++) {
            int e = i * 256 + tid;
            int b = e >> 7, f4 = e & 127;
            cp_async16(&rh_s[b * 520 + f4 * 4], g_rhx + gid * 2048 + b * 512 + f4 * 4);
        }
        cp_commit(); cp_wait<0>(); __syncthreads();

        // ---- Phase B dot: g, 4 cols per lane ----
        {
            float ag[4] = {0.f, 0.f, 0.f, 0.f};
            const float* rp = rh_s + lb * 520 + kbase;
#pragma unroll
            for (int k4 = 0; k4 < 16; k4++) {
                float4 h4 = *(const float4*)(rp + k4 * 4);
                int fs = ((((kbase >> 2) + k4) ^ cg) << 2);
#pragma unroll
                for (int ci = 0; ci < 4; ci++) {
                    float4 w1 = *(const float4*)(wg + (cc0 + ci) * 512 + fs);
                    ag[ci] += h4.x * w1.x + h4.y * w1.y + h4.z * w1.z + h4.w * w1.w;
                }
            }
#pragma unroll
            for (int ci = 0; ci < 4; ci++)
                red[kw * 264 + lb * 33 + cc0 + ci] = ag[ci];
        }
        __syncthreads();

        // ---- Phase B reduce + h update ----
        float hn = 0.f;
        if (tid < 128) {
            int b = tid >> 5, col = tid & 31;
            float s = pG;
#pragma unroll
            for (int w = 0; w < 8; w++) s += red[w * 264 + b * 33 + col];
            float g = tanhf(s);
            float z = z_s[tid];
            float ho = h_s[b * 520 + c0 + col];
            hn = z * ho + (1.f - z) * g;
            __stcg(&g_hx[gid * 2048 + b * 512 + c0 + col], hn);
        }
        __syncthreads();
        if (tid == 0) grp_arrive(bar);
        ep++;

        // ---- barrier B shadow: Hout + next Abuf prefetch ----
        if (tid < 128)
            Hout[(size_t)(t * 32 + b0 + (tid >> 5)) * 512 + c0 + (tid & 31)] = hn;
        if (t + 1 < SS) {
            const float* ab = Abuf + (size_t)((t + 1) * 32 + b0 + rb) * 1536;
            pA = __ldg(ab + rg * 512 + c0 + rcol);
            if (tid < 128) pG = __ldg(ab + 1024 + c0 + rcol);
        }

        if (tid == 0) grp_wait(bar, ep * 16);
        __syncthreads();
    }
}

// ---------------- hidden-state tail (h at t = SS-1 from Hout) ----------------
__global__ void copy_hidden_kernel(float* __restrict__ out,
                                   const float* __restrict__ H0f,
                                   const float* __restrict__ H1f) {
    int i = blockIdx.x * 256 + threadIdx.x;   // (B, L, H)
    if (i < BB * 2 * HH) {
        int b = i >> 10, rem = i & 1023;
        int l = rem >> 9, h = rem & 511;
        const float* src = l ? H1f : H0f;
        out[i] = src[(size_t)((SS - 1) * 32 + b) * 512 + h];
    }
}

// ---------------- launch ----------------
extern "C" void kernel_launch(void* const* d_in, const int* in_sizes, int n_in,
                              void* d_out, int out_size)
{
    const float* x    = (const float*)d_in[0];
    const float* h0   = (const float*)d_in[1];
    const float* W0xz = (const float*)d_in[2];
    const float* W0hz = (const float*)d_in[3];
    const float* b0z  = (const float*)d_in[4];
    const float* W0xr = (const float*)d_in[5];
    const float* W0hr = (const float*)d_in[6];
    const float* b0r  = (const float*)d_in[7];
    const float* W0xg = (const float*)d_in[8];
    const float* W0hg = (const float*)d_in[9];
    const float* b0g  = (const float*)d_in[10];
    const float* W1xz = (const float*)d_in[11];
    const float* W1hz = (const float*)d_in[12];
    const float* b1z  = (const float*)d_in[13];
    const float* W1xr = (const float*)d_in[14];
    const float* W1hr = (const float*)d_in[15];
    const float* b1r  = (const float*)d_in[16];
    const float* W1xg = (const float*)d_in[17];
    const float* W1hg = (const float*)d_in[18];
    const float* b1g  = (const float*)d_in[19];
    const float* Wy   = (const float*)d_in[20];
    const float* by   = (const float*)d_in[21];
    float* out = (float*)d_out;

    float *Abuf, *H0, *H1;
    cudaGetSymbolAddress((void**)&Abuf, g_Abuf);
    cudaGetSymbolAddress((void**)&H0,   g_H0);
    cudaGetSymbolAddress((void**)&H1,   g_H1);

    // smem: 3*WSZ + h 4*520 + rh 4*520 + red 8*264 + z 128 = 55552 floats
    const size_t smem = (size_t)(3 * WSZ + 8 * 520 + 8 * 264 + 128) * sizeof(float);
    cudaFuncSetAttribute(gru_group_kernel,
                         cudaFuncAttributeMaxDynamicSharedMemorySize, (int)smem);

    dim3 gproj(512, 12);  // M=65536/128, N=1536/128

    // layer 0
    sgemm_kernel<<<gproj, 256>>>(x, 0, II, W0xz, W0xr, W0xg, b0z, b0r, b0g,
                                 512, Abuf, 0, 1536);
    init_hx_kernel<<<64, 256>>>(h0, 0);
    reset_bar_kernel<<<1, 32>>>();
    gru_group_kernel<<<RGRID, 256, smem>>>(Abuf, W0hz, W0hr, W0hg, H0);

    // layer 1
    sgemm_kernel<<<gproj, 256>>>(H0, 1, HH, W1xz, W1xr, W1xg, b1z, b1r, b1g,
                                 512, Abuf, 0, 1536);
    init_hx_kernel<<<64, 256>>>(h0, 1);
    reset_bar_kernel<<<1, 32>>>();
    gru_group_kernel<<<RGRID, 256, smem>>>(Abuf, W1hz, W1hr, W1hg, H1);

    // output head
    dim3 ghead(512, 1);
    sgemm_kernel<<<ghead, 256>>>(H1, 1, HH, Wy, Wy, Wy, by, by, by,
                                 128, out, 1, 0);

    if (out_size >= BB * SS * OO + BB * 2 * HH) {
        copy_hidden_kernel<<<128, 256>>>(out + BB * SS * OO, H0, H1);
    }
}

// round 12
// speedup vs baseline: 2.1318x; 1.0206x over previous
#include <cuda_runtime.h>
#include <math.h>
#include <stdint.h>

// Problem dims
#define BB 32
#define SS 2048
#define II 128
#define HH 512
#define OO 128

#define RGRID 128        // 8 groups x 16 CTAs
#define WSZ (32 * 512)   // per-gate weight floats in SMEM (32 cols)

// packed f32x2 FMA (FFMA2) — only reachable via PTX
#define FMA2(acc, a, b) \
    asm("fma.rn.f32x2 %0, %1, %2, %0;" : "+l"(acc) : "l"(a), "l"(b))
#define PACK2(d, s) \
    asm("mov.b64 %0, {%1, %1};" : "=l"(d) : "f"(s))
#define UNPACK2(lo, hi, v) \
    asm("mov.b64 {%0, %1}, %2;" : "=f"(lo), "=f"(hi) : "l"(v))

// ---------------- static device scratch ----------------
__device__ float g_Abuf[SS * BB * 1536];  // x-projections [t][b][z|r|g]
__device__ float g_H0[SS * BB * HH];
__device__ float g_H1[SS * BB * HH];
__device__ float g_hx[BB * HH];           // group-exchanged h   [gbatch][512]
__device__ float g_rhx[BB * HH];          // group-exchanged r*h [gbatch][512]
__device__ unsigned g_gbar[8 * 32];       // per-group barrier counters (128B apart)

// ---------------- cp.async helpers ----------------
__device__ __forceinline__ void cp_async16(void* smem, const void* gmem) {
    unsigned s = (unsigned)__cvta_generic_to_shared(smem);
    asm volatile("cp.async.cg.shared.global [%0], [%1], 16;" :: "r"(s), "l"(gmem));
}
__device__ __forceinline__ void cp_commit() {
    asm volatile("cp.async.commit_group;");
}
template<int N> __device__ __forceinline__ void cp_wait() {
    asm volatile("cp.async.wait_group %0;" :: "n"(N));
}

// ---------------- per-group barrier (16 arrivals) ----------------
__device__ __forceinline__ void grp_arrive(unsigned* bar) {
    asm volatile("red.release.gpu.global.add.u32 [%0], %1;"
                 :: "l"(bar), "r"(1u) : "memory");
}
__device__ __forceinline__ void grp_wait(unsigned* bar, unsigned tgt) {
    unsigned v;
    do {
        asm volatile("ld.acquire.gpu.global.u32 %0, [%1];"
                     : "=r"(v) : "l"(bar) : "memory");
    } while (v < tgt);
}

__global__ void reset_bar_kernel() {
    int i = threadIdx.x;
    if (i < 8) g_gbar[i * 32] = 0;
}

// init group-exchange h from h0 (B, L, H) for one layer
__global__ void init_hx_kernel(const float* __restrict__ h0, int layer) {
    int i = blockIdx.x * 256 + threadIdx.x;   // 32*512
    if (i < BB * HH) {
        int gb = i >> 9, c = i & 511;
        g_hx[i] = h0[gb * 1024 + layer * 512 + c];
    }
}

// ---------------- SGEMM (R10 structure + f32x2 inner product) ----------------
__global__ __launch_bounds__(256, 2) void sgemm_kernel(
    const float* __restrict__ A, int amode, int K,
    const float* __restrict__ W0g, const float* __restrict__ W1g, const float* __restrict__ W2g,
    const float* __restrict__ b0g, const float* __restrict__ b1g, const float* __restrict__ b2g,
    int ngate, float* __restrict__ C, int omode, int ldc)
{
    __shared__ float As[8][128];
    __shared__ float Bs[8][132];

    const int tid = threadIdx.x;
    const int bm = blockIdx.x;
    const int ncol0 = blockIdx.y * 128;
    const int gate = ncol0 / ngate;
    const float* W    = (gate == 0) ? W0g : (gate == 1) ? W1g : W2g;
    const float* bias = (gate == 0) ? b0g : (gate == 1) ? b1g : b2g;
    const int ng_off = ncol0 - gate * ngate;

    const int tx = tid & 15;
    const int ty = tid >> 4;

    unsigned long long acc2[8][4];
#pragma unroll
    for (int i = 0; i < 8; i++)
#pragma unroll
        for (int j = 0; j < 4; j++) acc2[i][j] = 0ull;

    const int arow = tid >> 1;
    const int ak = (tid & 1) * 4;
    const int grow = bm * 128 + arow;
    long aoff;
    if (amode == 0) aoff = (long)(grow & 31) * (SS * II) + (long)(grow >> 5) * II;
    else            aoff = (long)grow * K;

    const int bk = tid >> 5;
    const int bn = (tid & 31) * 4;

    for (int kk = 0; kk < K; kk += 8) {
        float4 av = *(const float4*)(A + aoff + (kk + ak));
        As[ak + 0][arow] = av.x;
        As[ak + 1][arow] = av.y;
        As[ak + 2][arow] = av.z;
        As[ak + 3][arow] = av.w;
        float4 wv = *(const float4*)(W + (long)(kk + bk) * ngate + (ng_off + bn));
        *(float4*)&Bs[bk][bn] = wv;
        __syncthreads();
#pragma unroll
        for (int k = 0; k < 8; k++) {
            float rm[8];
            *(float4*)&rm[0] = *(const float4*)&As[k][ty * 8];
            *(float4*)&rm[4] = *(const float4*)&As[k][ty * 8 + 4];
            ulonglong2 rp0 = *(const ulonglong2*)&Bs[k][tx * 8];
            ulonglong2 rp1 = *(const ulonglong2*)&Bs[k][tx * 8 + 4];
            unsigned long long rn2[4] = {rp0.x, rp0.y, rp1.x, rp1.y};
#pragma unroll
            for (int i = 0; i < 8; i++) {
                unsigned long long rmd;
                PACK2(rmd, rm[i]);
#pragma unroll
                for (int j = 0; j < 4; j++)
                    FMA2(acc2[i][j], rmd, rn2[j]);
            }
        }
        __syncthreads();
    }

#pragma unroll
    for (int i = 0; i < 8; i++) {
        int row = bm * 128 + ty * 8 + i;
        long obase;
        if (omode == 0) obase = (long)row * ldc + ncol0;
        else            obase = (long)(row & 31) * (SS * OO) + (long)(row >> 5) * OO + ncol0;
#pragma unroll
        for (int j = 0; j < 4; j++) {
            float lo, hi;
            UNPACK2(lo, hi, acc2[i][j]);
            C[obase + tx * 8 + j * 2]     = lo + bias[ng_off + tx * 8 + j * 2];
            C[obase + tx * 8 + j * 2 + 1] = hi + bias[ng_off + tx * 8 + j * 2 + 1];
        }
    }
}

// ---------------- grouped GRU recurrence (R10 structure + f32x2 dots) ----------------
// Group = 16 CTAs = 4 batches (b0..b0+3); CTA rank owns 32 columns.
// All exchange (r*h, h) stays inside the group -> 16-arrival barrier.
__global__ void __launch_bounds__(256, 1) gru_group_kernel(
    const float* __restrict__ Abuf,
    const float* __restrict__ Whz, const float* __restrict__ Whr, const float* __restrict__ Whg,
    float* __restrict__ Hout)
{
    extern __shared__ float smf[];
    float* wz   = smf;                 // [32][512] swizzled
    float* wr   = wz + WSZ;
    float* wg   = wr + WSZ;
    float* h_s  = wg + WSZ;            // [4][520]
    float* rh_s = h_s + 4 * 520;       // [4][520]
    float* red  = rh_s + 4 * 520;      // [8 warps][264] : g*132 + b*33 + col
    float* z_s  = red + 8 * 264;       // [128] : b*32 + col

    const int tid = threadIdx.x;
    const int cta = blockIdx.x;
    const int gid = cta >> 4, rank = cta & 15;
    const int c0 = rank * 32;
    const int b0 = gid * 4;
    const int lane = tid & 31, kw = tid >> 5;
    const int kbase = kw * 64;
    const int lb = lane & 3;           // batch within group
    const int cg = lane >> 2;          // col group of 4
    const int cc0 = cg * 4;
    // reduce mapping
    const int rg = tid >> 7;           // 0=z, 1=r
    const int rb = (tid >> 5) & 3;
    const int rcol = tid & 31;

    // ---- stage weights swizzled: (cc,f) at cc*512 + ((f^(cc>>2))<<2 | ki) ----
    for (int idx = tid; idx < 3 * WSZ; idx += 256) {
        int m = idx >> 14;
        int rem = idx & 16383;
        int cc = rem >> 9, k = rem & 511;
        const float* Wm = (m == 0) ? Whz : (m == 1) ? Whr : Whg;
        float v = Wm[k * 512 + c0 + cc];
        int f = k >> 2, ki = k & 3;
        smf[m * WSZ + cc * 512 + ((((f ^ (cc >> 2)) << 2)) | ki)] = v;
    }
    __syncthreads();

    unsigned* bar = &g_gbar[gid * 32];
    unsigned ep = 0;

    // t=0 Abuf prefetch
    float pA, pG = 0.f;
    {
        const float* ab = Abuf + (size_t)(b0 + rb) * 1536;
        pA = __ldg(ab + rg * 512 + c0 + rcol);
        if (tid < 128) pG = __ldg(ab + 1024 + c0 + rcol);
    }

    for (int t = 0; t < SS; t++) {
        // ---- stage h (4x512 = 8KB) ----
#pragma unroll
        for (int i = 0; i < 2; i++) {
            int e = i * 256 + tid;         // 0..511 float4
            int b = e >> 7, f4 = e & 127;
            cp_async16(&h_s[b * 520 + f4 * 4], g_hx + gid * 2048 + b * 512 + f4 * 4);
        }
        cp_commit(); cp_wait<0>(); __syncthreads();

        // ---- Phase A dot: z & r, 4 cols x 2 gates per lane, f32x2 pairs ----
        {
            unsigned long long az2[4] = {0ull, 0ull, 0ull, 0ull};
            unsigned long long ar2[4] = {0ull, 0ull, 0ull, 0ull};
            const float* hp = h_s + lb * 520 + kbase;
#pragma unroll
            for (int k4 = 0; k4 < 16; k4++) {
                ulonglong2 h2 = *(const ulonglong2*)(hp + k4 * 4);
                int fs = ((((kbase >> 2) + k4) ^ cg) << 2);
#pragma unroll
                for (int ci = 0; ci < 4; ci++) {
                    ulonglong2 w1 = *(const ulonglong2*)(wz + (cc0 + ci) * 512 + fs);
                    FMA2(az2[ci], h2.x, w1.x);
                    FMA2(az2[ci], h2.y, w1.y);
                    ulonglong2 w2 = *(const ulonglong2*)(wr + (cc0 + ci) * 512 + fs);
                    FMA2(ar2[ci], h2.x, w2.x);
                    FMA2(ar2[ci], h2.y, w2.y);
                }
            }
#pragma unroll
            for (int ci = 0; ci < 4; ci++) {
                float lo, hi;
                UNPACK2(lo, hi, az2[ci]);
                red[kw * 264 +       lb * 33 + cc0 + ci] = lo + hi;
                UNPACK2(lo, hi, ar2[ci]);
                red[kw * 264 + 132 + lb * 33 + cc0 + ci] = lo + hi;
            }
        }
        __syncthreads();

        // ---- Phase A reduce + activations + rh store ----
        {
            float s = pA;
#pragma unroll
            for (int w = 0; w < 8; w++) s += red[w * 264 + rg * 132 + rb * 33 + rcol];
            float sg = 1.f / (1.f + __expf(-s));
            if (rg == 0) {
                z_s[rb * 32 + rcol] = sg;
            } else {
                float rh = sg * h_s[rb * 520 + c0 + rcol];
                __stcg(&g_rhx[gid * 2048 + rb * 512 + c0 + rcol], rh);
            }
        }
        __syncthreads();
        if (tid == 0) grp_arrive(bar);
        ep++;
        if (tid == 0) grp_wait(bar, ep * 16);
        __syncthreads();

        // ---- stage r*h ----
#pragma unroll
        for (int i = 0; i < 2; i++) {
            int e = i * 256 + tid;
            int b = e >> 7, f4 = e & 127;
            cp_async16(&rh_s[b * 520 + f4 * 4], g_rhx + gid * 2048 + b * 512 + f4 * 4);
        }
        cp_commit(); cp_wait<0>(); __syncthreads();

        // ---- Phase B dot: g, 4 cols per lane, f32x2 pairs ----
        {
            unsigned long long ag2[4] = {0ull, 0ull, 0ull, 0ull};
            const float* rp = rh_s + lb * 520 + kbase;
#pragma unroll
            for (int k4 = 0; k4 < 16; k4++) {
                ulonglong2 h2 = *(const ulonglong2*)(rp + k4 * 4);
                int fs = ((((kbase >> 2) + k4) ^ cg) << 2);
#pragma unroll
                for (int ci = 0; ci < 4; ci++) {
                    ulonglong2 w1 = *(const ulonglong2*)(wg + (cc0 + ci) * 512 + fs);
                    FMA2(ag2[ci], h2.x, w1.x);
                    FMA2(ag2[ci], h2.y, w1.y);
                }
            }
#pragma unroll
            for (int ci = 0; ci < 4; ci++) {
                float lo, hi;
                UNPACK2(lo, hi, ag2[ci]);
                red[kw * 264 + lb * 33 + cc0 + ci] = lo + hi;
            }
        }
        __syncthreads();

        // ---- Phase B reduce + h update ----
        float hn = 0.f;
        if (tid < 128) {
            int b = tid >> 5, col = tid & 31;
            float s = pG;
#pragma unroll
            for (int w = 0; w < 8; w++) s += red[w * 264 + b * 33 + col];
            float g = tanhf(s);
            float z = z_s[tid];
            float ho = h_s[b * 520 + c0 + col];
            hn = z * ho + (1.f - z) * g;
            __stcg(&g_hx[gid * 2048 + b * 512 + c0 + col], hn);
        }
        __syncthreads();
        if (tid == 0) grp_arrive(bar);
        ep++;

        // ---- barrier B shadow: Hout + next Abuf prefetch ----
        if (tid < 128)
            Hout[(size_t)(t * 32 + b0 + (tid >> 5)) * 512 + c0 + (tid & 31)] = hn;
        if (t + 1 < SS) {
            const float* ab = Abuf + (size_t)((t + 1) * 32 + b0 + rb) * 1536;
            pA = __ldg(ab + rg * 512 + c0 + rcol);
            if (tid < 128) pG = __ldg(ab + 1024 + c0 + rcol);
        }

        if (tid == 0) grp_wait(bar, ep * 16);
        __syncthreads();
    }
}

// ---------------- hidden-state tail (h at t = SS-1 from Hout) ----------------
__global__ void copy_hidden_kernel(float* __restrict__ out,
                                   const float* __restrict__ H0f,
                                   const float* __restrict__ H1f) {
    int i = blockIdx.x * 256 + threadIdx.x;   // (B, L, H)
    if (i < BB * 2 * HH) {
        int b = i >> 10, rem = i & 1023;
        int l = rem >> 9, h = rem & 511;
        const float* src = l ? H1f : H0f;
        out[i] = src[(size_t)((SS - 1) * 32 + b) * 512 + h];
    }
}

// ---------------- launch ----------------
extern "C" void kernel_launch(void* const* d_in, const int* in_sizes, int n_in,
                              void* d_out, int out_size)
{
    const float* x    = (const float*)d_in[0];
    const float* h0   = (const float*)d_in[1];
    const float* W0xz = (const float*)d_in[2];
    const float* W0hz = (const float*)d_in[3];
    const float* b0z  = (const float*)d_in[4];
    const float* W0xr = (const float*)d_in[5];
    const float* W0hr = (const float*)d_in[6];
    const float* b0r  = (const float*)d_in[7];
    const float* W0xg = (const float*)d_in[8];
    const float* W0hg = (const float*)d_in[9];
    const float* b0g  = (const float*)d_in[10];
    const float* W1xz = (const float*)d_in[11];
    const float* W1hz = (const float*)d_in[12];
    const float* b1z  = (const float*)d_in[13];
    const float* W1xr = (const float*)d_in[14];
    const float* W1hr = (const float*)d_in[15];
    const float* b1r  = (const float*)d_in[16];
    const float* W1xg = (const float*)d_in[17];
    const float* W1hg = (const float*)d_in[18];
    const float* b1g  = (const float*)d_in[19];
    const float* Wy   = (const float*)d_in[20];
    const float* by   = (const float*)d_in[21];
    float* out = (float*)d_out;

    float *Abuf, *H0, *H1;
    cudaGetSymbolAddress((void**)&Abuf, g_Abuf);
    cudaGetSymbolAddress((void**)&H0,   g_H0);
    cudaGetSymbolAddress((void**)&H1,   g_H1);

    // smem: 3*WSZ + h 4*520 + rh 4*520 + red 8*264 + z 128
    const size_t smem = (size_t)(3 * WSZ + 8 * 520 + 8 * 264 + 128) * sizeof(float);
    cudaFuncSetAttribute(gru_group_kernel,
                         cudaFuncAttributeMaxDynamicSharedMemorySize, (int)smem);

    dim3 gproj(512, 12);  // M=65536/128, N=1536/128

    // layer 0
    sgemm_kernel<<<gproj, 256>>>(x, 0, II, W0xz, W0xr, W0xg, b0z, b0r, b0g,
                                 512, Abuf, 0, 1536);
    init_hx_kernel<<<64, 256>>>(h0, 0);
    reset_bar_kernel<<<1, 32>>>();
    gru_group_kernel<<<RGRID, 256, smem>>>(Abuf, W0hz, W0hr, W0hg, H0);

    // layer 1
    sgemm_kernel<<<gproj, 256>>>(H0, 1, HH, W1xz, W1xr, W1xg, b1z, b1r, b1g,
                                 512, Abuf, 0, 1536);
    init_hx_kernel<<<64, 256>>>(h0, 1);
    reset_bar_kernel<<<1, 32>>>();
    gru_group_kernel<<<RGRID, 256, smem>>>(Abuf, W1hz, W1hr, W1hg, H1);

    // output head
    dim3 ghead(512, 1);
    sgemm_kernel<<<ghead, 256>>>(H1, 1, HH, Wy, Wy, Wy, by, by, by,
                                 128, out, 1, 0);

    if (out_size >= BB * SS * OO + BB * 2 * HH) {
        copy_hidden_kernel<<<128, 256>>>(out + BB * SS * OO, H0, H1);
    }
}

// round 13
// speedup vs baseline: 2.1403x; 1.0040x over previous
#include <cuda_runtime.h>
#include <math.h>
#include <stdint.h>

// Problem dims
#define BB 32
#define SS 2048
#define II 128
#define HH 512
#define OO 128

#define RGRID 128        // 8 groups x 16 CTAs

// packed f32x2 FMA (FFMA2) — only reachable via PTX
#define FMA2(acc, a, b) \
    asm("fma.rn.f32x2 %0, %1, %2, %0;" : "+l"(acc) : "l"(a), "l"(b))
#define PACK2(d, s) \
    asm("mov.b64 %0, {%1, %1};" : "=l"(d) : "f"(s))
#define UNPACK2(lo, hi, v) \
    asm("mov.b64 {%0, %1}, %2;" : "=f"(lo), "=f"(hi) : "l"(v))

// ---------------- static device scratch ----------------
__device__ float g_Abuf[SS * BB * 1536];  // x-projections [t][b][z|r|g]
__device__ float g_H0[SS * BB * HH];
__device__ float g_H1[SS * BB * HH];
__device__ float g_zrP[8][16][2][4][512]; // partial z/r pre-acts per writer CTA
__device__ float g_gP[8][16][4][512];     // partial g pre-acts per writer CTA
__device__ unsigned g_gbar[8 * 32];       // per-group barrier counters (128B apart)

// ---------------- per-group barrier (16 arrivals) ----------------
__device__ __forceinline__ void grp_arrive(unsigned* bar) {
    asm volatile("red.release.gpu.global.add.u32 [%0], %1;"
                 :: "l"(bar), "r"(1u) : "memory");
}
__device__ __forceinline__ void grp_wait(unsigned* bar, unsigned tgt) {
    unsigned v;
    do {
        asm volatile("ld.acquire.gpu.global.u32 %0, [%1];"
                     : "=r"(v) : "l"(bar) : "memory");
    } while (v < tgt);
}

__global__ void reset_bar_kernel() {
    int i = threadIdx.x;
    if (i < 8) g_gbar[i * 32] = 0;
}

// ---------------- SGEMM (R11, known-good) ----------------
__global__ __launch_bounds__(256, 2) void sgemm_kernel(
    const float* __restrict__ A, int amode, int K,
    const float* __restrict__ W0g, const float* __restrict__ W1g, const float* __restrict__ W2g,
    const float* __restrict__ b0g, const float* __restrict__ b1g, const float* __restrict__ b2g,
    int ngate, float* __restrict__ C, int omode, int ldc)
{
    __shared__ float As[8][128];
    __shared__ float Bs[8][132];

    const int tid = threadIdx.x;
    const int bm = blockIdx.x;
    const int ncol0 = blockIdx.y * 128;
    const int gate = ncol0 / ngate;
    const float* W    = (gate == 0) ? W0g : (gate == 1) ? W1g : W2g;
    const float* bias = (gate == 0) ? b0g : (gate == 1) ? b1g : b2g;
    const int ng_off = ncol0 - gate * ngate;

    const int tx = tid & 15;
    const int ty = tid >> 4;

    unsigned long long acc2[8][4];
#pragma unroll
    for (int i = 0; i < 8; i++)
#pragma unroll
        for (int j = 0; j < 4; j++) acc2[i][j] = 0ull;

    const int arow = tid >> 1;
    const int ak = (tid & 1) * 4;
    const int grow = bm * 128 + arow;
    long aoff;
    if (amode == 0) aoff = (long)(grow & 31) * (SS * II) + (long)(grow >> 5) * II;
    else            aoff = (long)grow * K;

    const int bk = tid >> 5;
    const int bn = (tid & 31) * 4;

    for (int kk = 0; kk < K; kk += 8) {
        float4 av = *(const float4*)(A + aoff + (kk + ak));
        As[ak + 0][arow] = av.x;
        As[ak + 1][arow] = av.y;
        As[ak + 2][arow] = av.z;
        As[ak + 3][arow] = av.w;
        float4 wv = *(const float4*)(W + (long)(kk + bk) * ngate + (ng_off + bn));
        *(float4*)&Bs[bk][bn] = wv;
        __syncthreads();
#pragma unroll
        for (int k = 0; k < 8; k++) {
            float rm[8];
            *(float4*)&rm[0] = *(const float4*)&As[k][ty * 8];
            *(float4*)&rm[4] = *(const float4*)&As[k][ty * 8 + 4];
            ulonglong2 rp0 = *(const ulonglong2*)&Bs[k][tx * 8];
            ulonglong2 rp1 = *(const ulonglong2*)&Bs[k][tx * 8 + 4];
            unsigned long long rn2[4] = {rp0.x, rp0.y, rp1.x, rp1.y};
#pragma unroll
            for (int i = 0; i < 8; i++) {
                unsigned long long rmd;
                PACK2(rmd, rm[i]);
#pragma unroll
                for (int j = 0; j < 4; j++)
                    FMA2(acc2[i][j], rmd, rn2[j]);
            }
        }
        __syncthreads();
    }

#pragma unroll
    for (int i = 0; i < 8; i++) {
        int row = bm * 128 + ty * 8 + i;
        long obase;
        if (omode == 0) obase = (long)row * ldc + ncol0;
        else            obase = (long)(row & 31) * (SS * OO) + (long)(row >> 5) * OO + ncol0;
#pragma unroll
        for (int j = 0; j < 4; j++) {
            float lo, hi;
            UNPACK2(lo, hi, acc2[i][j]);
            C[obase + tx * 8 + j * 2]     = lo + bias[ng_off + tx * 8 + j * 2];
            C[obase + tx * 8 + j * 2 + 1] = hi + bias[ng_off + tx * 8 + j * 2 + 1];
        }
    }
}

// ---------------- partial-sum GRU recurrence ----------------
// Group = 16 CTAs = 4 batches; CTA rank owns h-columns [32r, 32r+32) — which
// are exactly the k-rows it needs to compute partial pre-activations for ALL
// 512 output columns. No operand exchange: only partial sums cross CTAs
// (fixed per-writer slots, no atomics, deterministic). 2 barriers/step.
__global__ void __launch_bounds__(256, 1) gru_part_kernel(
    const float* __restrict__ Abuf,
    const float* __restrict__ Whz, const float* __restrict__ Whr, const float* __restrict__ Whg,
    const float* __restrict__ h0, int layer, float* __restrict__ Hout)
{
    extern __shared__ float smf[];
    float* wz = smf;             // [32 k][512 c'] row slices
    float* wr = wz + 16384;
    float* wg = wr + 16384;
    unsigned long long* hdup  = (unsigned long long*)(wg + 16384); // [32 k][4 b] {h,h}
    unsigned long long* rhdup = hdup + 128;                        // [32 k][4 b] {rh,rh}
    float* hO  = (float*)(rhdup + 128);   // [4 b][32 c] own h
    float* z_s = hO + 128;                // [4 b][32 c]

    const int tid = threadIdx.x;
    const int cta = blockIdx.x;
    const int gid = cta >> 4, rank = cta & 15;
    const int c0 = rank * 32;             // owned cols == owned k-rows
    const int b0 = gid * 4;
    const int ct = tid;                   // owned c'-pair (2ct, 2ct+1)
    // reader mapping (256 threads = 2 gates x 4 b x 32 c; tid<128 => gate z)
    const int rg = tid >> 7, rb = (tid >> 5) & 3, rc = tid & 31;

    // ---- stage weight ROWS k in [c0, c0+32), all 512 cols ----
    for (int idx = tid; idx < 3 * 16384; idx += 256) {
        int m = idx >> 14, rem = idx & 16383;
        int k = rem >> 9, c = rem & 511;
        const float* Wm = (m == 0) ? Whz : (m == 1) ? Whr : Whg;
        smf[m * 16384 + rem] = Wm[(c0 + k) * 512 + c];
    }
    // ---- init own h ----
    if (tid < 128) {
        float h = h0[(b0 + rb) * 1024 + layer * 512 + c0 + rc];
        hO[tid] = h;
        unsigned long long hd; PACK2(hd, h);
        hdup[rc * 4 + rb] = hd;
    }
    __syncthreads();

    unsigned* bar = &g_gbar[gid * 32];
    unsigned ep = 0;

    const unsigned long long* wz2 = (const unsigned long long*)wz;
    const unsigned long long* wr2 = (const unsigned long long*)wr;
    const unsigned long long* wg2 = (const unsigned long long*)wg;

    float* zrW = &g_zrP[gid][rank][0][0][0];
    float* gW  = &g_gP[gid][rank][0][0];
    const float* zrR = &g_zrP[gid][0][rg][rb][c0 + rc];
    const float* gR  = &g_gP[gid][0][(tid >> 5) & 3][c0 + (tid & 31)];

    // t=0 Abuf prefetch
    float pA, pG = 0.f;
    {
        const float* ab = Abuf + (size_t)(b0 + rb) * 1536;
        pA = __ldg(ab + rg * 512 + c0 + rc);
        if (tid < 128) pG = __ldg(ab + 1024 + c0 + rc);
    }

    for (int t = 0; t < SS; t++) {
        // ---- ZR partial dot: my 32 k-rows -> all 512 c' (pairs), 4 b, 2 gates ----
        {
            unsigned long long az[4] = {0,0,0,0}, ar[4] = {0,0,0,0};
#pragma unroll
            for (int k = 0; k < 32; k++) {
                unsigned long long wzv = wz2[k * 256 + ct];
                unsigned long long wrv = wr2[k * 256 + ct];
                ulonglong2 h01 = *(const ulonglong2*)&hdup[k * 4];
                ulonglong2 h23 = *(const ulonglong2*)&hdup[k * 4 + 2];
                FMA2(az[0], h01.x, wzv); FMA2(ar[0], h01.x, wrv);
                FMA2(az[1], h01.y, wzv); FMA2(ar[1], h01.y, wrv);
                FMA2(az[2], h23.x, wzv); FMA2(ar[2], h23.x, wrv);
                FMA2(az[3], h23.y, wzv); FMA2(ar[3], h23.y, wrv);
            }
#pragma unroll
            for (int b = 0; b < 4; b++) {
                __stcg((double*)(zrW + b * 512) + ct,       __longlong_as_double(az[b]));
                __stcg((double*)(zrW + (4 + b) * 512) + ct, __longlong_as_double(ar[b]));
            }
        }
        __syncthreads();
        if (tid == 0) grp_arrive(bar);
        ep++;
        if (tid == 0) grp_wait(bar, ep * 16);
        __syncthreads();

        // ---- read zr partials (MLP 16) + activations ----
        {
            float s = pA;
#pragma unroll
            for (int w = 0; w < 16; w++) s += __ldcg(zrR + w * 4096);
            float sg = 1.f / (1.f + __expf(-s));
            if (rg == 0) {
                z_s[tid] = sg;
            } else {
                float rh = sg * hO[rb * 32 + rc];
                unsigned long long rd; PACK2(rd, rh);
                rhdup[rc * 4 + rb] = rd;
            }
        }
        __syncthreads();

        // ---- G partial dot ----
        {
            unsigned long long ag[4] = {0,0,0,0};
#pragma unroll
            for (int k = 0; k < 32; k++) {
                unsigned long long wgv = wg2[k * 256 + ct];
                ulonglong2 r01 = *(const ulonglong2*)&rhdup[k * 4];
                ulonglong2 r23 = *(const ulonglong2*)&rhdup[k * 4 + 2];
                FMA2(ag[0], r01.x, wgv);
                FMA2(ag[1], r01.y, wgv);
                FMA2(ag[2], r23.x, wgv);
                FMA2(ag[3], r23.y, wgv);
            }
#pragma unroll
            for (int b = 0; b < 4; b++)
                __stcg((double*)(gW + b * 512) + ct, __longlong_as_double(ag[b]));
        }
        __syncthreads();
        if (tid == 0) grp_arrive(bar);
        ep++;

        // ---- barrier shadow: next step's Abuf prefetch ----
        float npA = 0.f, npG = 0.f;
        if (t + 1 < SS) {
            const float* ab = Abuf + (size_t)((t + 1) * 32 + b0 + rb) * 1536;
            npA = __ldg(ab + rg * 512 + c0 + rc);
            if (tid < 128) npG = __ldg(ab + 1024 + c0 + rc);
        }

        if (tid == 0) grp_wait(bar, ep * 16);
        __syncthreads();

        // ---- read g partials + h update (owners = tid<128) ----
        if (tid < 128) {
            float s = pG;
#pragma unroll
            for (int w = 0; w < 16; w++) s += __ldcg(gR + w * 2048);
            float g = tanhf(s);
            float z = z_s[tid];
            float ho = hO[tid];
            float hn = z * ho + (1.f - z) * g;
            hO[tid] = hn;
            unsigned long long hd; PACK2(hd, hn);
            hdup[rc * 4 + rb] = hd;
            Hout[(size_t)(t * 32 + b0 + rb) * 512 + c0 + rc] = hn;
        }
        pA = npA; pG = npG;
        __syncthreads();
    }
}

// ---------------- hidden-state tail (h at t = SS-1 from Hout) ----------------
__global__ void copy_hidden_kernel(float* __restrict__ out,
                                   const float* __restrict__ H0f,
                                   const float* __restrict__ H1f) {
    int i = blockIdx.x * 256 + threadIdx.x;   // (B, L, H)
    if (i < BB * 2 * HH) {
        int b = i >> 10, rem = i & 1023;
        int l = rem >> 9, h = rem & 511;
        const float* src = l ? H1f : H0f;
        out[i] = src[(size_t)((SS - 1) * 32 + b) * 512 + h];
    }
}

// ---------------- launch ----------------
extern "C" void kernel_launch(void* const* d_in, const int* in_sizes, int n_in,
                              void* d_out, int out_size)
{
    const float* x    = (const float*)d_in[0];
    const float* h0   = (const float*)d_in[1];
    const float* W0xz = (const float*)d_in[2];
    const float* W0hz = (const float*)d_in[3];
    const float* b0z  = (const float*)d_in[4];
    const float* W0xr = (const float*)d_in[5];
    const float* W0hr = (const float*)d_in[6];
    const float* b0r  = (const float*)d_in[7];
    const float* W0xg = (const float*)d_in[8];
    const float* W0hg = (const float*)d_in[9];
    const float* b0g  = (const float*)d_in[10];
    const float* W1xz = (const float*)d_in[11];
    const float* W1hz = (const float*)d_in[12];
    const float* b1z  = (const float*)d_in[13];
    const float* W1xr = (const float*)d_in[14];
    const float* W1hr = (const float*)d_in[15];
    const float* b1r  = (const float*)d_in[16];
    const float* W1xg = (const float*)d_in[17];
    const float* W1hg = (const float*)d_in[18];
    const float* b1g  = (const float*)d_in[19];
    const float* Wy   = (const float*)d_in[20];
    const float* by   = (const float*)d_in[21];
    float* out = (float*)d_out;

    float *Abuf, *H0, *H1;
    cudaGetSymbolAddress((void**)&Abuf, g_Abuf);
    cudaGetSymbolAddress((void**)&H0,   g_H0);
    cudaGetSymbolAddress((void**)&H1,   g_H1);

    // smem: 3*16384 weights + hdup 256 + rhdup 256 + hO 128 + z 128 floats
    const size_t smem = (size_t)(3 * 16384 + 256 + 256 + 128 + 128) * sizeof(float);
    cudaFuncSetAttribute(gru_part_kernel,
                         cudaFuncAttributeMaxDynamicSharedMemorySize, (int)smem);

    dim3 gproj(512, 12);  // M=65536/128, N=1536/128

    // layer 0
    sgemm_kernel<<<gproj, 256>>>(x, 0, II, W0xz, W0xr, W0xg, b0z, b0r, b0g,
                                 512, Abuf, 0, 1536);
    reset_bar_kernel<<<1, 32>>>();
    gru_part_kernel<<<RGRID, 256, smem>>>(Abuf, W0hz, W0hr, W0hg, h0, 0, H0);

    // layer 1
    sgemm_kernel<<<gproj, 256>>>(H0, 1, HH, W1xz, W1xr, W1xg, b1z, b1r, b1g,
                                 512, Abuf, 0, 1536);
    reset_bar_kernel<<<1, 32>>>();
    gru_part_kernel<<<RGRID, 256, smem>>>(Abuf, W1hz, W1hr, W1hg, h0, 1, H1);

    // output head
    dim3 ghead(512, 1);
    sgemm_kernel<<<ghead, 256>>>(H1, 1, HH, Wy, Wy, Wy, by, by, by,
                                 128, out, 1, 0);

    if (out_size >= BB * SS * OO + BB * 2 * HH) {
        copy_hidden_kernel<<<128, 256>>>(out + BB * SS * OO, H0, H1);
    }
}